// round 10
// baseline (speedup 1.0000x reference)
#include <cuda_runtime.h>
#include <cstdint>
#include <math.h>

// Problem constants (fixed by the reference)
#define NUM_K    1024      // primitives / codebook size
#define NUM_ROWS 32768     // 8 * 4096 tokens
#define DIM_D    1024      // embedding dim

#define TINY_F   1.17549435e-38f
#define LN2_F    0.693147180559945f
#define T_SMALL  4e-3f     // clamp floor for MUFU-approx t; below -> force exact in phase 2
#define U_FORCE  0.99599f  // u > U_FORCE  <=>  t < ~4.017e-3 (covers clamped band w/ margin)
#define CAND_EPS 3e-4f     // >3x proven |z_approx - z_exact| bound for unclamped elems
#define NEG_INF  __int_as_float(0xff800000)

// add via IMAD on the fma pipe: a*one + b (one==1, opaque kernel arg so ptxas
// cannot fold it back to IADD3 on the saturated alu pipe)
__device__ __forceinline__ uint32_t addf(uint32_t a, uint32_t b, uint32_t one) {
    uint32_t r;
    asm("mad.lo.u32 %0, %1, %2, %3;" : "=r"(r) : "r"(a), "r"(one), "r"(b));
    return r;
}

// ---------------------------------------------------------------------------
// Threefry-2x32, 20 rounds, key = (0, 42) (jax.random.key(42)).
// Partitionable-mode 32-bit harvest: counter=(0, elem_idx); out = x0 ^ x1.
// SHF rotates (alu, locked); ALL adds forced to IMAD (fma pipe) to unload alu.
// ---------------------------------------------------------------------------
__device__ __forceinline__ uint32_t tf_rotl(uint32_t x, int r) {
    return (x << r) | (x >> (32 - r));
}

__device__ __forceinline__ uint32_t threefry_xor(uint32_t c1, uint32_t one) {
    const uint32_t ks1 = 42u;
    const uint32_t ks2 = 0x1BD11BDAu ^ 42u;
    uint32_t x0 = 0u;
    uint32_t x1 = addf(c1, ks1, one);
#define TF_R(r) { x0 = addf(x1, x0, one); x1 = tf_rotl(x1, (r)); x1 ^= x0; }
    TF_R(13) TF_R(15) TF_R(26) TF_R(6)
    x0 = addf(x0, ks1, one);      x1 = addf(x1, ks2 + 1u, one);
    TF_R(17) TF_R(29) TF_R(16) TF_R(24)
    x0 = addf(x0, ks2, one);      x1 = addf(x1, 0u + 2u, one);
    TF_R(13) TF_R(15) TF_R(26) TF_R(6)
    x0 = addf(x0, 0u, one);       x1 = addf(x1, ks1 + 3u, one);
    TF_R(17) TF_R(29) TF_R(16) TF_R(24)
    x0 = addf(x0, ks1, one);      x1 = addf(x1, ks2 + 4u, one);
    TF_R(13) TF_R(15) TF_R(26) TF_R(6)
    x0 = addf(x0, ks2, one);      x1 = addf(x1, 0u + 5u, one);
#undef TF_R
    return x0 ^ x1;
}

// Exact gumbel: identical formula/precision to the reference (XLA lowers log ->
// libdevice logf = CUDA accurate logf). Clamp applied here (cold path).
__device__ __forceinline__ float gumbel_exact(float f) {
    float u = fmaxf(f, TINY_F);
    return -logf(-logf(u));
}

// ---------------------------------------------------------------------------
// Tiny pre-kernel: zero the counts region of out (poisoned 0xAA by harness).
// Launch order [zero, fused] keeps ncu "-s 5" on the fused kernel.
// ---------------------------------------------------------------------------
__global__ void vybn_zero_counts(float* __restrict__ out, long long out_elems) {
    int k = threadIdx.x;
    long long off = (long long)NUM_ROWS * DIM_D + NUM_ROWS + k;
    if (off < out_elems) out[off] = 0.0f;
}

// ---------------------------------------------------------------------------
// One block per row.
// Phase 1 (straight-line): MUFU-based z~ with tt clamped at T_SMALL (za is a
//   LOWER bound in the clamped region -> gmax never inflated -> screen sound).
//   No u-clamp here: f==0 (P=2^-23/elem) yields za=-inf, a sound lower bound;
//   such an element winning needs max-of-1024 gumbels < ~1 (P ~ e^-376).
// Phase 2: candidates = (z~ >= gmax-CAND_EPS) OR (u > U_FORCE). Exact z
//   (accurate logf) only for candidates; argmax over exact values.
// Then gather primitives[idx] -> out; counts via float atomicAdd into out.
// ---------------------------------------------------------------------------
__global__ __launch_bounds__(256, 2)
void vybn_fused_kernel(const float* __restrict__ logits,
                       const float* __restrict__ prim,
                       float* __restrict__ out,
                       long long out_elems,
                       uint32_t one) {
    const int row  = blockIdx.x;
    const int t    = threadIdx.x;
    const int lane = t & 31;
    const int warp = t >> 5;

    // each thread handles k in [4t, 4t+4)
    const float4 lv = ((const float4*)(logits + (size_t)row * NUM_K))[t];
    const float lvi[4] = {lv.x, lv.y, lv.z, lv.w};
    const uint32_t base = (uint32_t)row * (uint32_t)NUM_K + (uint32_t)(4 * t);

    float u[4];   // raw uniform (unclamped), kept for the exact rescue path
    float za[4];  // z approx (lower bound in the clamped region)
    float zmax = NEG_INF;

    #pragma unroll
    for (int i = 0; i < 4; i++) {
        uint32_t bits = threefry_xor(base + (uint32_t)i, one);
        float f = __uint_as_float((bits >> 9) | 0x3f800000u) - 1.0f;
        u[i] = f;
        // t~ = -ln(u) via MUFU.LG2 + FMUL; clamp so za error is bounded
        float tt  = __log2f(f) * (-LN2_F);
        float ttc = fmaxf(tt, T_SMALL);
        za[i] = fmaf(__log2f(ttc), -LN2_F, lvi[i]);
        zmax = fmaxf(zmax, za[i]);
    }

    // block max of z~ (values only)
    #pragma unroll
    for (int off = 16; off > 0; off >>= 1)
        zmax = fmaxf(zmax, __shfl_xor_sync(0xFFFFFFFFu, zmax, off));

    __shared__ float swv[8];
    __shared__ float swe[8];
    __shared__ int   swi[8];
    __shared__ int   s_idx;
    if (lane == 0) swv[warp] = zmax;
    __syncthreads();

    float gmax = swv[0];
    #pragma unroll
    for (int w = 1; w < 8; w++) gmax = fmaxf(gmax, swv[w]);
    const float thresh = gmax - CAND_EPS;

    // Phase 2: exact evaluation for candidates only (inline logf; rare)
    float best = NEG_INF;
    int   bidx = 4 * t;
    #pragma unroll
    for (int i = 0; i < 4; i++) {
        if ((za[i] >= thresh) || (u[i] > U_FORCE)) {
            float ze = lvi[i] + gumbel_exact(u[i]);
            if (ze > best) { best = ze; bidx = 4 * t + i; }
        }
    }

    // warp argmax (ties -> lower index)
    #pragma unroll
    for (int off = 16; off > 0; off >>= 1) {
        float ov = __shfl_down_sync(0xFFFFFFFFu, best, off);
        int   oi = __shfl_down_sync(0xFFFFFFFFu, bidx, off);
        if (ov > best || (ov == best && oi < bidx)) { best = ov; bidx = oi; }
    }
    if (lane == 0) { swe[warp] = best; swi[warp] = bidx; }
    __syncthreads();

    if (t == 0) {
        best = swe[0]; bidx = swi[0];
        #pragma unroll
        for (int w = 1; w < 8; w++) {
            float ov = swe[w]; int oi = swi[w];
            if (ov > best || (ov == best && oi < bidx)) { best = ov; bidx = oi; }
        }
        s_idx = bidx;
        // counts: exact order-independent float accumulation (adds of 1.0f)
        long long coff = (long long)NUM_ROWS * DIM_D + NUM_ROWS + bidx;
        if (coff < out_elems) atomicAdd(&out[coff], 1.0f);
        long long ioff = (long long)NUM_ROWS * DIM_D + row;
        if (ioff < out_elems) out[ioff] = (float)bidx;
    }
    __syncthreads();

    const int idx = s_idx;
    // embeddings row = primitives[idx] exactly (hard one-hot forward)
    float4 v = ((const float4*)(prim + (size_t)idx * DIM_D))[t];
    ((float4*)(out + (size_t)row * DIM_D))[t] = v;
}

extern "C" void kernel_launch(void* const* d_in, const int* in_sizes, int n_in,
                              void* d_out, int out_size) {
    const float* logits = (const float*)d_in[0];
    const float* prim   = (const float*)d_in[1];
    if (n_in >= 2 && in_sizes[0] < in_sizes[1]) {
        const float* tmp = logits; logits = prim; prim = tmp;
    }
    float* out = (float*)d_out;

    vybn_zero_counts<<<1, NUM_K>>>(out, (long long)out_size);
    vybn_fused_kernel<<<NUM_ROWS, 256>>>(logits, prim, out, (long long)out_size, 1u);
}

// round 11
// speedup vs baseline: 1.0002x; 1.0002x over previous
#include <cuda_runtime.h>
#include <cstdint>
#include <math.h>

// Problem constants (fixed by the reference)
#define NUM_K    1024      // primitives / codebook size
#define NUM_ROWS 32768     // 8 * 4096 tokens
#define DIM_D    1024      // embedding dim

#define TINY_F   1.17549435e-38f
#define LN2_F    0.693147180559945f
#define T_SMALL  4e-3f     // clamp floor for MUFU-approx t; below -> force exact in phase 2
#define U_FORCE  0.99599f  // u > U_FORCE  <=>  t < ~4.017e-3 (covers clamped band w/ margin)
#define CAND_EPS 3e-4f     // >3x proven |z_approx - z_exact| bound for unclamped elems
#define NEG_INF  __int_as_float(0xff800000)

// add via IMAD on the fma pipe: a*one + b (one==1, opaque kernel arg so ptxas
// cannot fold it back to IADD3 on the saturated alu pipe)
__device__ __forceinline__ uint32_t addf(uint32_t a, uint32_t b, uint32_t one) {
    uint32_t r;
    asm("mad.lo.u32 %0, %1, %2, %3;" : "=r"(r) : "r"(a), "r"(one), "r"(b));
    return r;
}

// hi 32 bits of bits * 2^23  ==  bits >> 9, on the fma pipe (IMAD.WIDE).
// Off the threefry critical chain (feeds MUFU; latency hidden by 4-elem ILP).
__device__ __forceinline__ uint32_t shr9_fma(uint32_t bits) {
    uint64_t p;
    asm("mul.wide.u32 %0, %1, %2;" : "=l"(p) : "r"(bits), "r"(1u << 23));
    return (uint32_t)(p >> 32);
}

// ---------------------------------------------------------------------------
// Threefry-2x32, 20 rounds, key = (0, 42) (jax.random.key(42)).
// Partitionable-mode 32-bit harvest: counter=(0, elem_idx); out = x0 ^ x1.
// SHF rotates (alu, locked); adds forced to IMAD (fma pipe).
// Takes base and the folded constant (42 + elem_offset) so the per-element
// counter add merges into the first key injection: one IMAD total.
// ---------------------------------------------------------------------------
__device__ __forceinline__ uint32_t tf_rotl(uint32_t x, int r) {
    return (x << r) | (x >> (32 - r));
}

__device__ __forceinline__ uint32_t threefry_xor(uint32_t base, uint32_t k42i, uint32_t one) {
    const uint32_t ks1 = 42u;
    const uint32_t ks2 = 0x1BD11BDAu ^ 42u;
    uint32_t x0 = 0u;
    uint32_t x1 = addf(base, k42i, one);   // == (base + i) + 42, single IMAD
#define TF_R(r) { x0 = addf(x1, x0, one); x1 = tf_rotl(x1, (r)); x1 ^= x0; }
    TF_R(13) TF_R(15) TF_R(26) TF_R(6)
    x0 = addf(x0, ks1, one);      x1 = addf(x1, ks2 + 1u, one);
    TF_R(17) TF_R(29) TF_R(16) TF_R(24)
    x0 = addf(x0, ks2, one);      x1 = addf(x1, 0u + 2u, one);
    TF_R(13) TF_R(15) TF_R(26) TF_R(6)
    x0 = addf(x0, 0u, one);       x1 = addf(x1, ks1 + 3u, one);
    TF_R(17) TF_R(29) TF_R(16) TF_R(24)
    x0 = addf(x0, ks1, one);      x1 = addf(x1, ks2 + 4u, one);
    TF_R(13) TF_R(15) TF_R(26) TF_R(6)
    x0 = addf(x0, ks2, one);      x1 = addf(x1, 0u + 5u, one);
#undef TF_R
    return x0 ^ x1;
}

// Exact gumbel: identical formula/precision to the reference (XLA lowers log ->
// libdevice logf = CUDA accurate logf). Clamp applied here (cold path).
__device__ __forceinline__ float gumbel_exact(float f) {
    float u = fmaxf(f, TINY_F);
    return -logf(-logf(u));
}

// ---------------------------------------------------------------------------
// Tiny pre-kernel: zero the counts region of out (poisoned 0xAA by harness).
// Launch order [zero, fused] keeps ncu "-s 5" on the fused kernel.
// ---------------------------------------------------------------------------
__global__ void vybn_zero_counts(float* __restrict__ out, long long out_elems) {
    int k = threadIdx.x;
    long long off = (long long)NUM_ROWS * DIM_D + NUM_ROWS + k;
    if (off < out_elems) out[off] = 0.0f;
}

// ---------------------------------------------------------------------------
// One block per row.
// Phase 1 (straight-line): MUFU-based z~ with tt clamped at T_SMALL (za is a
//   LOWER bound in the clamped region -> gmax never inflated -> screen sound).
// Phase 2: candidates = (z~ >= gmax-CAND_EPS) OR (u > U_FORCE). Exact z
//   (accurate logf) only for candidates; argmax over exact values.
// Then gather primitives[idx] -> out; counts via float atomicAdd into out.
// ---------------------------------------------------------------------------
__global__ __launch_bounds__(256, 2)
void vybn_fused_kernel(const float* __restrict__ logits,
                       const float* __restrict__ prim,
                       float* __restrict__ out,
                       long long out_elems,
                       uint32_t one) {
    const int row  = blockIdx.x;
    const int t    = threadIdx.x;
    const int lane = t & 31;
    const int warp = t >> 5;

    // each thread handles k in [4t, 4t+4)
    const float4 lv = ((const float4*)(logits + (size_t)row * NUM_K))[t];
    const float lvi[4] = {lv.x, lv.y, lv.z, lv.w};
    const uint32_t base = (uint32_t)row * (uint32_t)NUM_K + (uint32_t)(4 * t);

    float u[4];   // raw uniform (unclamped), kept for the exact rescue path
    float za[4];  // z approx (lower bound in the clamped region)
    float zmax = NEG_INF;

    #pragma unroll
    for (int i = 0; i < 4; i++) {
        uint32_t bits = threefry_xor(base, 42u + (uint32_t)i, one);
        // (bits>>9)|0x3f800000 computed entirely on the fma pipe:
        uint32_t mant = shr9_fma(bits);                  // IMAD.WIDE hi
        float f = __uint_as_float(addf(mant, 0x3f800000u, one)) - 1.0f;
        u[i] = f;
        // t~ = -ln(u) via MUFU.LG2 + FMUL; clamp so za error is bounded
        float tt  = __log2f(f) * (-LN2_F);
        float ttc = fmaxf(tt, T_SMALL);
        za[i] = fmaf(__log2f(ttc), -LN2_F, lvi[i]);
        zmax = fmaxf(zmax, za[i]);
    }

    // block max of z~ (values only)
    #pragma unroll
    for (int off = 16; off > 0; off >>= 1)
        zmax = fmaxf(zmax, __shfl_xor_sync(0xFFFFFFFFu, zmax, off));

    __shared__ float swv[8];
    __shared__ float swe[8];
    __shared__ int   swi[8];
    __shared__ int   s_idx;
    if (lane == 0) swv[warp] = zmax;
    __syncthreads();

    float gmax = swv[0];
    #pragma unroll
    for (int w = 1; w < 8; w++) gmax = fmaxf(gmax, swv[w]);
    const float thresh = gmax - CAND_EPS;

    // Phase 2: exact evaluation for candidates only (inline logf; rare)
    float best = NEG_INF;
    int   bidx = 4 * t;
    #pragma unroll
    for (int i = 0; i < 4; i++) {
        if ((za[i] >= thresh) || (u[i] > U_FORCE)) {
            float ze = lvi[i] + gumbel_exact(u[i]);
            if (ze > best) { best = ze; bidx = 4 * t + i; }
        }
    }

    // warp argmax (ties -> lower index)
    #pragma unroll
    for (int off = 16; off > 0; off >>= 1) {
        float ov = __shfl_down_sync(0xFFFFFFFFu, best, off);
        int   oi = __shfl_down_sync(0xFFFFFFFFu, bidx, off);
        if (ov > best || (ov == best && oi < bidx)) { best = ov; bidx = oi; }
    }
    if (lane == 0) { swe[warp] = best; swi[warp] = bidx; }
    __syncthreads();

    if (t == 0) {
        best = swe[0]; bidx = swi[0];
        #pragma unroll
        for (int w = 1; w < 8; w++) {
            float ov = swe[w]; int oi = swi[w];
            if (ov > best || (ov == best && oi < bidx)) { best = ov; bidx = oi; }
        }
        s_idx = bidx;
        // counts: exact order-independent float accumulation (adds of 1.0f)
        long long coff = (long long)NUM_ROWS * DIM_D + NUM_ROWS + bidx;
        if (coff < out_elems) atomicAdd(&out[coff], 1.0f);
        long long ioff = (long long)NUM_ROWS * DIM_D + row;
        if (ioff < out_elems) out[ioff] = (float)bidx;
    }
    __syncthreads();

    const int idx = s_idx;
    // embeddings row = primitives[idx] exactly (hard one-hot forward)
    float4 v = ((const float4*)(prim + (size_t)idx * DIM_D))[t];
    ((float4*)(out + (size_t)row * DIM_D))[t] = v;
}

extern "C" void kernel_launch(void* const* d_in, const int* in_sizes, int n_in,
                              void* d_out, int out_size) {
    const float* logits = (const float*)d_in[0];
    const float* prim   = (const float*)d_in[1];
    if (n_in >= 2 && in_sizes[0] < in_sizes[1]) {
        const float* tmp = logits; logits = prim; prim = tmp;
    }
    float* out = (float*)d_out;

    vybn_zero_counts<<<1, NUM_K>>>(out, (long long)out_size);
    vybn_fused_kernel<<<NUM_ROWS, 256>>>(logits, prim, out, (long long)out_size, 1u);
}

// round 12
// speedup vs baseline: 1.1226x; 1.1223x over previous
#include <cuda_runtime.h>
#include <cstdint>
#include <math.h>

// Problem constants (fixed by the reference)
#define NUM_K    1024      // primitives / codebook size
#define NUM_ROWS 32768     // 8 * 4096 tokens
#define DIM_D    1024      // embedding dim

#define TINY_F   1.17549435e-38f
#define LN2_F    0.693147180559945f
#define T_SMALL  4e-3f     // clamp floor for MUFU-approx t; below -> force exact in phase 2
#define U_FORCE  0.99599f  // u > U_FORCE  <=>  t < ~4.017e-3 (covers clamped band w/ margin)
#define CAND_EPS 3e-4f     // >3x proven |z_approx - z_exact| bound for unclamped elems
#define NEG_INF  __int_as_float(0xff800000)

// add via IMAD on the fma pipe (one==1 is an opaque kernel arg; ptxas cannot
// fold it back to IADD3 on the alu pipe)
__device__ __forceinline__ uint32_t addf(uint32_t a, uint32_t b, uint32_t one) {
    uint32_t r;
    asm("mad.lo.u32 %0, %1, %2, %3;" : "=r"(r) : "r"(a), "r"(one), "r"(b));
    return r;
}

// bits>>9 as hi32(bits * 2^23) on the fma pipe (IMAD.WIDE), off the ARX chain
__device__ __forceinline__ uint32_t shr9_fma(uint32_t bits) {
    uint64_t p;
    asm("mul.wide.u32 %0, %1, %2;" : "=l"(p) : "r"(bits), "r"(1u << 23));
    return (uint32_t)(p >> 32);
}

// ---------------------------------------------------------------------------
// Threefry-2x32, 20 rounds, key = (0, 42) (jax.random.key(42)).
// Partitionable-mode 32-bit harvest: counter=(0, elem_idx); out = x0 ^ x1.
// SHF rotates (alu, locked); adds on IMAD (fma pipe). The per-element counter
// add is folded into the first key injection (base + (42 + elem_offset)).
// ---------------------------------------------------------------------------
__device__ __forceinline__ uint32_t tf_rotl(uint32_t x, int r) {
    return (x << r) | (x >> (32 - r));
}

__device__ __forceinline__ uint32_t threefry_xor(uint32_t base, uint32_t k42i, uint32_t one) {
    const uint32_t ks1 = 42u;
    const uint32_t ks2 = 0x1BD11BDAu ^ 42u;
    uint32_t x0 = 0u;
    uint32_t x1 = addf(base, k42i, one);   // == (base + off) + 42, single IMAD
#define TF_R(r) { x0 = addf(x1, x0, one); x1 = tf_rotl(x1, (r)); x1 ^= x0; }
    TF_R(13) TF_R(15) TF_R(26) TF_R(6)
    x0 = addf(x0, ks1, one);      x1 = addf(x1, ks2 + 1u, one);
    TF_R(17) TF_R(29) TF_R(16) TF_R(24)
    x0 = addf(x0, ks2, one);      x1 = addf(x1, 0u + 2u, one);
    TF_R(13) TF_R(15) TF_R(26) TF_R(6)
    x0 = addf(x0, 0u, one);       x1 = addf(x1, ks1 + 3u, one);
    TF_R(17) TF_R(29) TF_R(16) TF_R(24)
    x0 = addf(x0, ks1, one);      x1 = addf(x1, ks2 + 4u, one);
    TF_R(13) TF_R(15) TF_R(26) TF_R(6)
    x0 = addf(x0, ks2, one);      x1 = addf(x1, 0u + 5u, one);
#undef TF_R
    return x0 ^ x1;
}

// Exact gumbel: identical formula/precision to the reference (XLA lowers log ->
// libdevice logf = CUDA accurate logf). Clamp applied here (cold path).
__device__ __forceinline__ float gumbel_exact(float f) {
    float u = fmaxf(f, TINY_F);
    return -logf(-logf(u));
}

// ---------------------------------------------------------------------------
// Tiny pre-kernel: zero the counts region of out (poisoned 0xAA by harness).
// Launch order [zero, fused] keeps ncu "-s 5" on the fused kernel.
// ---------------------------------------------------------------------------
__global__ void vybn_zero_counts(float* __restrict__ out, long long out_elems) {
    int k = threadIdx.x;
    long long off = (long long)NUM_ROWS * DIM_D + NUM_ROWS + k;
    if (off < out_elems) out[off] = 0.0f;
}

// ---------------------------------------------------------------------------
// One block (128 threads) per row; 8 elements/thread for ILP.
// Thread t owns k in {4t..4t+3} U {512+4t..512+4t+3} (coalesced float4 pairs).
// Phase 1 (straight-line): MUFU z~ with tt clamped at T_SMALL (za = lower
//   bound in the clamped region -> gmax never inflated -> screen sound).
// Phase 2: candidates = (z~ >= gmax-CAND_EPS) OR (u > U_FORCE); exact z via
//   accurate logf for candidates only; argmax over exact values, min-index
//   tie-break (per-thread processing order is index-ascending).
// Then gather primitives[idx] -> out; counts via float atomicAdd into out.
// ---------------------------------------------------------------------------
__global__ __launch_bounds__(128)
void vybn_fused_kernel(const float* __restrict__ logits,
                       const float* __restrict__ prim,
                       float* __restrict__ out,
                       long long out_elems,
                       uint32_t one) {
    const int row  = blockIdx.x;
    const int t    = threadIdx.x;
    const int lane = t & 31;
    const int warp = t >> 5;

    const float4 lv0 = ((const float4*)(logits + (size_t)row * NUM_K))[t];
    const float4 lv1 = ((const float4*)(logits + (size_t)row * NUM_K))[t + 128];
    const float lvi[8] = {lv0.x, lv0.y, lv0.z, lv0.w, lv1.x, lv1.y, lv1.z, lv1.w};
    const uint32_t baseA = (uint32_t)row * (uint32_t)NUM_K + (uint32_t)(4 * t);

    float u[8];   // raw uniform (unclamped), kept for the exact rescue path
    float za[8];  // z approx (lower bound in the clamped region)
    float zmax = NEG_INF;

    #pragma unroll
    for (int i = 0; i < 8; i++) {
        const uint32_t koff = (i < 4) ? (uint32_t)i : (512u + (uint32_t)(i - 4));
        uint32_t bits = threefry_xor(baseA, 42u + koff, one);
        uint32_t mant = shr9_fma(bits);
        float f = __uint_as_float(addf(mant, 0x3f800000u, one)) - 1.0f;
        u[i] = f;
        float tt  = __log2f(f) * (-LN2_F);
        float ttc = fmaxf(tt, T_SMALL);
        za[i] = fmaf(__log2f(ttc), -LN2_F, lvi[i]);
        zmax = fmaxf(zmax, za[i]);
    }

    // warp max of z~
    #pragma unroll
    for (int off = 16; off > 0; off >>= 1)
        zmax = fmaxf(zmax, __shfl_xor_sync(0xFFFFFFFFu, zmax, off));

    __shared__ float swv[4];
    __shared__ float swe[4];
    __shared__ int   swi[4];
    __shared__ int   s_idx;
    if (lane == 0) swv[warp] = zmax;
    __syncthreads();

    float gmax = fmaxf(fmaxf(swv[0], swv[1]), fmaxf(swv[2], swv[3]));
    const float thresh = gmax - CAND_EPS;

    // Phase 2: exact evaluation for candidates only (inline logf; rare).
    // Per-thread processing order is index-ascending, so strict > keeps the
    // first occurrence (reference tie-break).
    float best = NEG_INF;
    int   bidx = 4 * t;
    #pragma unroll
    for (int i = 0; i < 8; i++) {
        if ((za[i] >= thresh) || (u[i] > U_FORCE)) {
            const int kidx = (i < 4) ? (4 * t + i) : (512 + 4 * t + (i - 4));
            float ze = lvi[i] + gumbel_exact(u[i]);
            if (ze > best) { best = ze; bidx = kidx; }
        }
    }

    // warp argmax (ties -> lower index)
    #pragma unroll
    for (int off = 16; off > 0; off >>= 1) {
        float ov = __shfl_down_sync(0xFFFFFFFFu, best, off);
        int   oi = __shfl_down_sync(0xFFFFFFFFu, bidx, off);
        if (ov > best || (ov == best && oi < bidx)) { best = ov; bidx = oi; }
    }
    if (lane == 0) { swe[warp] = best; swi[warp] = bidx; }
    __syncthreads();

    if (t == 0) {
        best = swe[0]; bidx = swi[0];
        #pragma unroll
        for (int w = 1; w < 4; w++) {
            float ov = swe[w]; int oi = swi[w];
            if (ov > best || (ov == best && oi < bidx)) { best = ov; bidx = oi; }
        }
        s_idx = bidx;
        // counts: exact order-independent float accumulation (adds of 1.0f)
        long long coff = (long long)NUM_ROWS * DIM_D + NUM_ROWS + bidx;
        if (coff < out_elems) atomicAdd(&out[coff], 1.0f);
        long long ioff = (long long)NUM_ROWS * DIM_D + row;
        if (ioff < out_elems) out[ioff] = (float)bidx;
    }
    __syncthreads();

    const int idx = s_idx;
    // embeddings row = primitives[idx] exactly (hard one-hot forward)
    float4 v0 = ((const float4*)(prim + (size_t)idx * DIM_D))[t];
    float4 v1 = ((const float4*)(prim + (size_t)idx * DIM_D))[t + 128];
    ((float4*)(out + (size_t)row * DIM_D))[t]       = v0;
    ((float4*)(out + (size_t)row * DIM_D))[t + 128] = v1;
}

extern "C" void kernel_launch(void* const* d_in, const int* in_sizes, int n_in,
                              void* d_out, int out_size) {
    const float* logits = (const float*)d_in[0];
    const float* prim   = (const float*)d_in[1];
    if (n_in >= 2 && in_sizes[0] < in_sizes[1]) {
        const float* tmp = logits; logits = prim; prim = tmp;
    }
    float* out = (float*)d_out;

    vybn_zero_counts<<<1, NUM_K>>>(out, (long long)out_size);
    vybn_fused_kernel<<<NUM_ROWS, 128>>>(logits, prim, out, (long long)out_size, 1u);
}

// round 13
// speedup vs baseline: 1.1591x; 1.0325x over previous
#include <cuda_runtime.h>
#include <cstdint>
#include <math.h>

// Problem constants (fixed by the reference)
#define NUM_K    1024      // primitives / codebook size
#define NUM_ROWS 32768     // 8 * 4096 tokens
#define DIM_D    1024      // embedding dim

#define TINY_F   1.17549435e-38f
#define LN2_F    0.693147180559945f
// clamp floor in w-space: w = -lg2(u); w < W_SMALL <=> t < 4e-3 (forced band)
#define W_SMALL  5.770780e-3f
#define U_FORCE  0.99599f  // u > U_FORCE  <=>  t < ~4.017e-3 (covers clamped band w/ margin)
#define CAND_EPS 3e-4f     // >3x proven |za' - (z_exact - C)| bound for unclamped elems
#define NEG_INF  __int_as_float(0xff800000)

// add via IMAD on the fma pipe (one==1 is an opaque kernel arg)
__device__ __forceinline__ uint32_t addf(uint32_t a, uint32_t b, uint32_t one) {
    uint32_t r;
    asm("mad.lo.u32 %0, %1, %2, %3;" : "=r"(r) : "r"(a), "r"(one), "r"(b));
    return r;
}

// bits>>9 as hi32(bits * 2^23) on the fma pipe (IMAD.WIDE)
__device__ __forceinline__ uint32_t shr9_fma(uint32_t bits) {
    uint64_t p;
    asm("mul.wide.u32 %0, %1, %2;" : "=l"(p) : "r"(bits), "r"(1u << 23));
    return (uint32_t)(p >> 32);
}

// order-preserving float->uint map (IEEE total order for non-NaN)
__device__ __forceinline__ uint32_t f2ord(float f) {
    uint32_t b = __float_as_uint(f);
    return b ^ ((uint32_t)((int)b >> 31) | 0x80000000u);
}
__device__ __forceinline__ float ord2f(uint32_t k) {
    uint32_t b = k ^ ((uint32_t)((int)(~k) >> 31) | 0x80000000u);
    return __uint_as_float(b);
}

__device__ __forceinline__ uint32_t redux_max_u32(uint32_t v) {
    uint32_t r;
    asm("redux.sync.max.u32 %0, %1, 0xffffffff;" : "=r"(r) : "r"(v));
    return r;
}
__device__ __forceinline__ int redux_min_s32(int v) {
    int r;
    asm("redux.sync.min.s32 %0, %1, 0xffffffff;" : "=r"(r) : "r"(v));
    return r;
}

// ---------------------------------------------------------------------------
// Threefry-2x32, 20 rounds, key = (0, 42). counter=(0, elem); out = x0^x1.
// SHF rotates (alu, locked); adds on IMAD (fma pipe); counter add folded into
// the first key injection.
// ---------------------------------------------------------------------------
__device__ __forceinline__ uint32_t tf_rotl(uint32_t x, int r) {
    return (x << r) | (x >> (32 - r));
}

__device__ __forceinline__ uint32_t threefry_xor(uint32_t base, uint32_t k42i, uint32_t one) {
    const uint32_t ks1 = 42u;
    const uint32_t ks2 = 0x1BD11BDAu ^ 42u;
    uint32_t x0 = 0u;
    uint32_t x1 = addf(base, k42i, one);
#define TF_R(r) { x0 = addf(x1, x0, one); x1 = tf_rotl(x1, (r)); x1 ^= x0; }
    TF_R(13) TF_R(15) TF_R(26) TF_R(6)
    x0 = addf(x0, ks1, one);      x1 = addf(x1, ks2 + 1u, one);
    TF_R(17) TF_R(29) TF_R(16) TF_R(24)
    x0 = addf(x0, ks2, one);      x1 = addf(x1, 0u + 2u, one);
    TF_R(13) TF_R(15) TF_R(26) TF_R(6)
    x0 = addf(x0, 0u, one);       x1 = addf(x1, ks1 + 3u, one);
    TF_R(17) TF_R(29) TF_R(16) TF_R(24)
    x0 = addf(x0, ks1, one);      x1 = addf(x1, ks2 + 4u, one);
    TF_R(13) TF_R(15) TF_R(26) TF_R(6)
    x0 = addf(x0, ks2, one);      x1 = addf(x1, 0u + 5u, one);
#undef TF_R
    return x0 ^ x1;
}

// Exact gumbel: identical formula/precision to the reference. Clamp here.
__device__ __forceinline__ float gumbel_exact(float f) {
    float u = fmaxf(f, TINY_F);
    return -logf(-logf(u));
}

__global__ void vybn_zero_counts(float* __restrict__ out, long long out_elems) {
    int k = threadIdx.x;
    long long off = (long long)NUM_ROWS * DIM_D + NUM_ROWS + k;
    if (off < out_elems) out[off] = 0.0f;
}

// ---------------------------------------------------------------------------
// One block (128 threads) per row; 8 elements/thread.
// Phase 1 (straight-line, 4 fp ops/elem): w = lg2(u) (<=0); wc = fmin(w,-W_SMALL);
//   za' = fma(lg2(-wc), -ln2, logit). All za' share the exact constant offset
//   -ln(ln2) vs true z, which cancels in max/threshold comparisons. Clamped
//   band (w > -W_SMALL, u near 1) gives a LOWER bound -> gmax never inflated.
// Phase 2: candidates = (za' >= gmax'-CAND_EPS) OR (u > U_FORCE); exact z via
//   accurate logf for candidates only; argmax over exact values, min-index
//   tie-break. Warp reductions via redux.sync on order-mapped bits.
// ---------------------------------------------------------------------------
__global__ __launch_bounds__(128)
void vybn_fused_kernel(const float* __restrict__ logits,
                       const float* __restrict__ prim,
                       float* __restrict__ out,
                       long long out_elems,
                       uint32_t one) {
    const int row  = blockIdx.x;
    const int t    = threadIdx.x;
    const int lane = t & 31;
    const int warp = t >> 5;

    const float4 lv0 = ((const float4*)(logits + (size_t)row * NUM_K))[t];
    const float4 lv1 = ((const float4*)(logits + (size_t)row * NUM_K))[t + 128];
    const float lvi[8] = {lv0.x, lv0.y, lv0.z, lv0.w, lv1.x, lv1.y, lv1.z, lv1.w};
    const uint32_t baseA = (uint32_t)row * (uint32_t)NUM_K + (uint32_t)(4 * t);

    float u[8];   // raw uniform (unclamped), kept for the exact rescue path
    float za[8];  // z approx minus constant (lower bound in the clamped region)
    float zmax = NEG_INF;

    #pragma unroll
    for (int i = 0; i < 8; i++) {
        const uint32_t koff = (i < 4) ? (uint32_t)i : (512u + (uint32_t)(i - 4));
        uint32_t bits = threefry_xor(baseA, 42u + koff, one);
        uint32_t mant = shr9_fma(bits);
        float f = __uint_as_float(addf(mant, 0x3f800000u, one)) - 1.0f;
        u[i] = f;
        float w  = __log2f(f);               // <= 0; MUFU.LG2
        float wc = fminf(w, -W_SMALL);       // clamp (forced band -> lower bound)
        za[i] = fmaf(__log2f(-wc), -LN2_F, lvi[i]);   // neg folds into MUFU src
        zmax = fmaxf(zmax, za[i]);
    }

    // warp max of za' via single redux on order-mapped bits
    uint32_t word = redux_max_u32(f2ord(zmax));

    __shared__ uint32_t swv[4];
    __shared__ uint32_t swe[4];
    __shared__ int      swi[4];
    __shared__ int      s_idx;
    if (lane == 0) swv[warp] = word;
    __syncthreads();

    uint32_t gord = max(max(swv[0], swv[1]), max(swv[2], swv[3]));
    const float thresh = ord2f(gord) - CAND_EPS;

    // Phase 2: exact evaluation for candidates only (inline logf; rare).
    float best = NEG_INF;
    int   bidx = 0x7FFFFFFF;
    #pragma unroll
    for (int i = 0; i < 8; i++) {
        if ((za[i] >= thresh) || (u[i] > U_FORCE)) {
            const int kidx = (i < 4) ? (4 * t + i) : (512 + 4 * t + (i - 4));
            float ze = lvi[i] + gumbel_exact(u[i]);
            // index-ascending order per thread -> strict > keeps first occurrence
            if (ze > best) { best = ze; bidx = kidx; }
        }
    }

    // warp argmax via redux: max of ord(best), then min index among matchers
    uint32_t bord = f2ord(best);
    uint32_t wmax = redux_max_u32(bord);
    int cidx = (bord == wmax) ? bidx : 0x7FFFFFFF;
    int widx = redux_min_s32(cidx);
    if (lane == 0) { swe[warp] = wmax; swi[warp] = widx; }
    __syncthreads();

    if (t == 0) {
        uint32_t bo = swe[0]; int bi = swi[0];
        #pragma unroll
        for (int w = 1; w < 4; w++) {
            if (swe[w] > bo || (swe[w] == bo && swi[w] < bi)) { bo = swe[w]; bi = swi[w]; }
        }
        s_idx = bi;
        long long coff = (long long)NUM_ROWS * DIM_D + NUM_ROWS + bi;
        if (coff < out_elems) atomicAdd(&out[coff], 1.0f);
        long long ioff = (long long)NUM_ROWS * DIM_D + row;
        if (ioff < out_elems) out[ioff] = (float)bi;
    }
    __syncthreads();

    const int idx = s_idx;
    // embeddings row = primitives[idx] exactly (hard one-hot forward)
    float4 v0 = ((const float4*)(prim + (size_t)idx * DIM_D))[t];
    float4 v1 = ((const float4*)(prim + (size_t)idx * DIM_D))[t + 128];
    ((float4*)(out + (size_t)row * DIM_D))[t]       = v0;
    ((float4*)(out + (size_t)row * DIM_D))[t + 128] = v1;
}

extern "C" void kernel_launch(void* const* d_in, const int* in_sizes, int n_in,
                              void* d_out, int out_size) {
    const float* logits = (const float*)d_in[0];
    const float* prim   = (const float*)d_in[1];
    if (n_in >= 2 && in_sizes[0] < in_sizes[1]) {
        const float* tmp = logits; logits = prim; prim = tmp;
    }
    float* out = (float*)d_out;

    vybn_zero_counts<<<1, NUM_K>>>(out, (long long)out_size);
    vybn_fused_kernel<<<NUM_ROWS, 128>>>(logits, prim, out, (long long)out_size, 1u);
}

// round 14
// speedup vs baseline: 1.1626x; 1.0030x over previous
#include <cuda_runtime.h>
#include <cstdint>
#include <math.h>

// Problem constants (fixed by the reference)
#define NUM_K    1024      // primitives / codebook size
#define NUM_ROWS 32768     // 8 * 4096 tokens
#define DIM_D    1024      // embedding dim

#define TINY_F   1.17549435e-38f
#define LN2_F    0.693147180559945f
// clamp floor in w-space: w = lg2(u) (<=0); w > -W_SMALL <=> t < 4e-3 (forced band)
#define W_SMALL  5.770780e-3f
#define U_FORCE  0.99599f  // u > U_FORCE covers the clamped band with margin
#define CAND_EPS 3e-4f     // >3x proven |za' - (z_exact - C)| bound for unclamped elems
#define NEG_INF  __int_as_float(0xff800000)

// add via IMAD on the fma pipe (one==1 is an opaque kernel arg)
__device__ __forceinline__ uint32_t addf(uint32_t a, uint32_t b, uint32_t one) {
    uint32_t r;
    asm("mad.lo.u32 %0, %1, %2, %3;" : "=r"(r) : "r"(a), "r"(one), "r"(b));
    return r;
}

// bits>>9 as hi32(bits * 2^23) on the fma pipe (IMAD.WIDE)
__device__ __forceinline__ uint32_t shr9_fma(uint32_t bits) {
    uint64_t p;
    asm("mul.wide.u32 %0, %1, %2;" : "=l"(p) : "r"(bits), "r"(1u << 23));
    return (uint32_t)(p >> 32);
}

// order-preserving float->uint map (IEEE total order for non-NaN)
__device__ __forceinline__ uint32_t f2ord(float f) {
    uint32_t b = __float_as_uint(f);
    return b ^ ((uint32_t)((int)b >> 31) | 0x80000000u);
}
__device__ __forceinline__ float ord2f(uint32_t k) {
    uint32_t b = k ^ ((uint32_t)((int)(~k) >> 31) | 0x80000000u);
    return __uint_as_float(b);
}

__device__ __forceinline__ uint32_t redux_max_u32(uint32_t v) {
    uint32_t r;
    asm("redux.sync.max.u32 %0, %1, 0xffffffff;" : "=r"(r) : "r"(v));
    return r;
}
__device__ __forceinline__ int redux_min_s32(int v) {
    int r;
    asm("redux.sync.min.s32 %0, %1, 0xffffffff;" : "=r"(r) : "r"(v));
    return r;
}

// ---------------------------------------------------------------------------
// Threefry-2x32, 20 rounds, key = (0, 42). counter=(0, elem); out = x0^x1.
// SHF rotates (alu, locked); adds on IMAD (fma pipe); counter add folded into
// the first key injection; round-1 "x0 += x1" peepholed (x0 starts at 0).
// ---------------------------------------------------------------------------
__device__ __forceinline__ uint32_t tf_rotl(uint32_t x, int r) {
    return (x << r) | (x >> (32 - r));
}

__device__ __forceinline__ uint32_t threefry_xor(uint32_t base, uint32_t k42i, uint32_t one) {
    const uint32_t ks1 = 42u;
    const uint32_t ks2 = 0x1BD11BDAu ^ 42u;
    uint32_t x1 = addf(base, k42i, one);
    uint32_t x0 = x1;                      // round-1 add with x0==0 peepholed
    x1 = tf_rotl(x1, 13) ^ x0;
#define TF_R(r) { x0 = addf(x1, x0, one); x1 = tf_rotl(x1, (r)); x1 ^= x0; }
    TF_R(15) TF_R(26) TF_R(6)
    x0 = addf(x0, ks1, one);      x1 = addf(x1, ks2 + 1u, one);
    TF_R(17) TF_R(29) TF_R(16) TF_R(24)
    x0 = addf(x0, ks2, one);      x1 = addf(x1, 0u + 2u, one);
    TF_R(13) TF_R(15) TF_R(26) TF_R(6)
    x0 = addf(x0, 0u, one);       x1 = addf(x1, ks1 + 3u, one);
    TF_R(17) TF_R(29) TF_R(16) TF_R(24)
    x0 = addf(x0, ks1, one);      x1 = addf(x1, ks2 + 4u, one);
    TF_R(13) TF_R(15) TF_R(26) TF_R(6)
    x0 = addf(x0, ks2, one);      x1 = addf(x1, 0u + 5u, one);
#undef TF_R
    return x0 ^ x1;
}

// Exact gumbel: identical formula/precision to the reference. Clamp here.
__device__ __forceinline__ float gumbel_exact(float f) {
    float u = fmaxf(f, TINY_F);
    return -logf(-logf(u));
}

__global__ void vybn_zero_counts(float* __restrict__ out, long long out_elems) {
    int k = threadIdx.x;
    long long off = (long long)NUM_ROWS * DIM_D + NUM_ROWS + k;
    if (off < out_elems) out[off] = 0.0f;
}

// ---------------------------------------------------------------------------
// One block (128 threads) per row; 8 elements/thread.
// Phase 1: za' = fma(lg2(-fmin(lg2(u), -W_SMALL)), -ln2, logit); track zmax
//   and umax per thread. Clamped band -> lower bound -> gmax never inflated.
// Phase 2 guarded PER THREAD: (zmax >= thresh) || (umax > U_FORCE) is exactly
//   the OR of the per-element candidacy tests -> only candidate threads run
//   the inner per-element tests + exact logf. Redux argmax outside the guard.
// ---------------------------------------------------------------------------
__global__ __launch_bounds__(128)
void vybn_fused_kernel(const float* __restrict__ logits,
                       const float* __restrict__ prim,
                       float* __restrict__ out,
                       long long out_elems,
                       uint32_t one) {
    const int row  = blockIdx.x;
    const int t    = threadIdx.x;
    const int lane = t & 31;
    const int warp = t >> 5;

    const float4 lv0 = ((const float4*)(logits + (size_t)row * NUM_K))[t];
    const float4 lv1 = ((const float4*)(logits + (size_t)row * NUM_K))[t + 128];
    const float lvi[8] = {lv0.x, lv0.y, lv0.z, lv0.w, lv1.x, lv1.y, lv1.z, lv1.w};
    const uint32_t baseA = (uint32_t)row * (uint32_t)NUM_K + (uint32_t)(4 * t);

    float u[8];   // raw uniform (unclamped), kept for the exact rescue path
    float za[8];  // z approx minus constant (lower bound in the clamped region)
    float zmax = NEG_INF;
    float umax = NEG_INF;

    #pragma unroll
    for (int i = 0; i < 8; i++) {
        const uint32_t koff = (i < 4) ? (uint32_t)i : (512u + (uint32_t)(i - 4));
        uint32_t bits = threefry_xor(baseA, 42u + koff, one);
        uint32_t mant = shr9_fma(bits);
        float f = __uint_as_float(addf(mant, 0x3f800000u, one)) - 1.0f;
        u[i] = f;
        umax = fmaxf(umax, f);
        float w  = __log2f(f);               // <= 0; MUFU.LG2
        float wc = fminf(w, -W_SMALL);       // clamp (forced band -> lower bound)
        za[i] = fmaf(__log2f(-wc), -LN2_F, lvi[i]);
        zmax = fmaxf(zmax, za[i]);
    }

    // warp max of za' via single redux on order-mapped bits
    uint32_t word = redux_max_u32(f2ord(zmax));

    __shared__ uint32_t swv[4];
    __shared__ uint32_t swe[4];
    __shared__ int      swi[4];
    __shared__ int      s_idx;
    if (lane == 0) swv[warp] = word;
    __syncthreads();

    uint32_t gord = max(max(swv[0], swv[1]), max(swv[2], swv[3]));
    const float thresh = ord2f(gord) - CAND_EPS;

    // Phase 2: thread-level guard == OR of per-element candidacy conditions
    float best = NEG_INF;
    int   bidx = 0x7FFFFFFF;
    if ((zmax >= thresh) || (umax > U_FORCE)) {
        #pragma unroll
        for (int i = 0; i < 8; i++) {
            if ((za[i] >= thresh) || (u[i] > U_FORCE)) {
                const int kidx = (i < 4) ? (4 * t + i) : (512 + 4 * t + (i - 4));
                float ze = lvi[i] + gumbel_exact(u[i]);
                // index-ascending per thread -> strict > keeps first occurrence
                if (ze > best) { best = ze; bidx = kidx; }
            }
        }
    }

    // warp argmax via redux: max of ord(best), then min index among matchers
    uint32_t bord = f2ord(best);
    uint32_t wmax = redux_max_u32(bord);
    int cidx = (bord == wmax) ? bidx : 0x7FFFFFFF;
    int widx = redux_min_s32(cidx);
    if (lane == 0) { swe[warp] = wmax; swi[warp] = widx; }
    __syncthreads();

    if (t == 0) {
        uint32_t bo = swe[0]; int bi = swi[0];
        #pragma unroll
        for (int w = 1; w < 4; w++) {
            if (swe[w] > bo || (swe[w] == bo && swi[w] < bi)) { bo = swe[w]; bi = swi[w]; }
        }
        s_idx = bi;
        long long coff = (long long)NUM_ROWS * DIM_D + NUM_ROWS + bi;
        if (coff < out_elems) atomicAdd(&out[coff], 1.0f);
        long long ioff = (long long)NUM_ROWS * DIM_D + row;
        if (ioff < out_elems) out[ioff] = (float)bi;
    }
    __syncthreads();

    const int idx = s_idx;
    // embeddings row = primitives[idx] exactly (hard one-hot forward)
    float4 v0 = ((const float4*)(prim + (size_t)idx * DIM_D))[t];
    float4 v1 = ((const float4*)(prim + (size_t)idx * DIM_D))[t + 128];
    ((float4*)(out + (size_t)row * DIM_D))[t]       = v0;
    ((float4*)(out + (size_t)row * DIM_D))[t + 128] = v1;
}

extern "C" void kernel_launch(void* const* d_in, const int* in_sizes, int n_in,
                              void* d_out, int out_size) {
    const float* logits = (const float*)d_in[0];
    const float* prim   = (const float*)d_in[1];
    if (n_in >= 2 && in_sizes[0] < in_sizes[1]) {
        const float* tmp = logits; logits = prim; prim = tmp;
    }
    float* out = (float*)d_out;

    vybn_zero_counts<<<1, NUM_K>>>(out, (long long)out_size);
    vybn_fused_kernel<<<NUM_ROWS, 128>>>(logits, prim, out, (long long)out_size, 1u);
}